// round 16
// baseline (speedup 1.0000x reference)
#include <cuda_runtime.h>
#include <cuda_fp16.h>

// Problem constants (fixed shapes):
//   x:      (16, 256, 64, 64)  fp32
//   weight: (8, 256)           fp32
//   bias:   (8,)               fp32
//   out:    (16, 256, 128, 128) fp32
#define Bn  16
#define Cn  256
#define Hn  64
#define Wn  64
#define OYn 128
#define OXn 128
#define PLANE (Hn * Wn)        // 4096
#define PADW 65                // padded row stride (uint2 cells), y-major
#define NPX  (OYn * OXn)       // 16384

// fp16-packed input, 4 channels per uint2 cell: [b][cg][h*64+w]. 32 MB.
__device__ uint2 g_xh[Bn * 64 * PLANE];
// Per-pixel sample descriptor (8 B): {half2(wx,wy),
//   base(14b) | dx<<14 | dy<<15 | zx0<<16 | zx1<<17 | zy0<<18 | zy1<<19}
__device__ uint2 g_samp[Bn * NPX];

__device__ __forceinline__ uint2 packh4(float a, float b, float c, float d)
{
    __half2 lo = __floats2half2_rn(a, b);
    __half2 hi = __floats2half2_rn(c, d);
    uint2 r;
    r.x = *reinterpret_cast<unsigned int*>(&lo);
    r.y = *reinterpret_cast<unsigned int*>(&hi);
    return r;
}

// Packed fp32x2 helpers (sm_103a FFMA2 — exact, two FMAs per issue slot).
#define PACK2(out, lo, hi) \
    asm("mov.b64 %0, {%1, %2};" : "=l"(out) : "f"(lo), "f"(hi))
#define UNPACK2(lo, hi, in) \
    asm("mov.b64 {%0, %1}, %2;" : "=f"(lo), "=f"(hi) : "l"(in))
#define FMA2(acc, a, b) \
    asm("fma.rn.f32x2 %0, %1, %2, %0;" : "+l"(acc) : "l"(a), "l"(b))

// ---------------------------------------------------------------------------
// Repack kernel (R10 form): x fp32 -> g_xh fp16x4 cells. Side stream,
// concurrent with stage1.
// ---------------------------------------------------------------------------
__global__ __launch_bounds__(256) void dysample_repack(
    const float* __restrict__ x)
{
    int idx = blockIdx.x * 256 + threadIdx.x;   // 0 .. 1,048,575
    int b   = idx >> 16;
    int r   = idx & 65535;
    int cg  = r >> 10;                          // 0..63
    int pi  = (r & 1023) * 4;                   // pixel base

    const float* p0 = x + ((size_t)b * Cn + (size_t)cg * 4) * PLANE + pi;
    float4 a = *reinterpret_cast<const float4*>(p0);
    float4 c = *reinterpret_cast<const float4*>(p0 + PLANE);
    float4 d = *reinterpret_cast<const float4*>(p0 + 2 * PLANE);
    float4 e = *reinterpret_cast<const float4*>(p0 + 3 * PLANE);

    uint2* dst = g_xh + ((size_t)(b * 64 + cg)) * PLANE + pi;
    uint2 c0 = packh4(a.x, c.x, d.x, e.x);
    uint2 c1 = packh4(a.y, c.y, d.y, e.y);
    uint2 c2 = packh4(a.z, c.z, d.z, e.z);
    uint2 c3 = packh4(a.w, c.w, d.w, e.w);
    *reinterpret_cast<uint4*>(dst)     = make_uint4(c0.x, c0.y, c1.x, c1.y);
    *reinterpret_cast<uint4*>(dst + 2) = make_uint4(c2.x, c2.y, c3.x, c3.y);
}

// ---------------------------------------------------------------------------
// Stage 1: 1x1 conv with VECTORIZED loads. Block = one (b, h) row.
// 256 threads = 16 pixel-quads (LDG.128 along w) x 16 channel-parts
// (16 ch each). LDG instruction count drops 4x vs scalar (the measured
// LSU-issue floor). FMAs stay packed f32x2.
// ---------------------------------------------------------------------------
__global__ __launch_bounds__(256) void dysample_stage1(
    const float* __restrict__ x,
    const float* __restrict__ weight,
    const float* __restrict__ bias)
{
    __shared__ float wt[Cn * 8];          // transposed: wt[c*8+o]
    __shared__ float part[8][16][64];     // [s][cpart][w]  32 KB

    for (int i = threadIdx.x; i < Cn * 8; i += 256)
        wt[(i & 255) * 8 + (i >> 8)] = weight[i];
    __syncthreads();

    int w4    = threadIdx.x & 15;         // pixel quad (w = w4*4 .. +3)
    int cpart = threadIdx.x >> 4;         // 0..15, 16 channels each
    int b     = blockIdx.x >> 6;
    int h     = blockIdx.x & 63;

    const float* xb  = x + ((size_t)b * Cn + cpart * 16) * PLANE
                         + h * Wn + w4 * 4;
    const float* wr0 = &wt[(cpart * 16) * 8];

    // acc2[j][p]: pixel j (0..3), s-pair p (s=2p, 2p+1)
    unsigned long long acc2[4][4];
#pragma unroll
    for (int j = 0; j < 4; ++j)
#pragma unroll
        for (int p = 0; p < 4; ++p) acc2[j][p] = 0;

#pragma unroll 4
    for (int c = 0; c < 16; ++c) {
        float4 xv = *reinterpret_cast<const float4*>(xb + (size_t)c * PLANE);
        float4 wa = *reinterpret_cast<const float4*>(wr0 + c * 8);
        float4 wb = *reinterpret_cast<const float4*>(wr0 + c * 8 + 4);
        unsigned long long w01, w23, w45, w67;
        PACK2(w01, wa.x, wa.y);
        PACK2(w23, wa.z, wa.w);
        PACK2(w45, wb.x, wb.y);
        PACK2(w67, wb.z, wb.w);
        float xj[4] = {xv.x, xv.y, xv.z, xv.w};
#pragma unroll
        for (int j = 0; j < 4; ++j) {
            unsigned long long x2;
            PACK2(x2, xj[j], xj[j]);
            FMA2(acc2[j][0], x2, w01);
            FMA2(acc2[j][1], x2, w23);
            FMA2(acc2[j][2], x2, w45);
            FMA2(acc2[j][3], x2, w67);
        }
    }

    // Store partials: for each s-pair, two float4 rows (4 pixels each).
#pragma unroll
    for (int p = 0; p < 4; ++p) {
        float lo[4], hi[4];
#pragma unroll
        for (int j = 0; j < 4; ++j) UNPACK2(lo[j], hi[j], acc2[j][p]);
        // contiguous STS.128: warp covers 512 B linear -> conflict-free
        *reinterpret_cast<float4*>(&part[2 * p][cpart][w4 * 4]) =
            make_float4(lo[0], lo[1], lo[2], lo[3]);
        *reinterpret_cast<float4*>(&part[2 * p + 1][cpart][w4 * 4]) =
            make_float4(hi[0], hi[1], hi[2], hi[3]);
    }
    __syncthreads();

    // Emit: 256 threads = 64 w x 4 s. Lane-stride-1 reads (conflict-free).
    {
        int w = threadIdx.x & 63;
        int s = threadIdx.x >> 6;         // 0..3
        float accx = __ldg(&bias[s]);
        float accy = __ldg(&bias[4 + s]);
#pragma unroll
        for (int k = 0; k < 16; ++k) {
            accx += part[s][k][w];
            accy += part[4 + s][k][w];
        }

        // pixel shuffle: out (oy=2h+r1, ox=2w+r2), s=r1*2+r2. Reference
        // quirk: x-coord uses h-linspace at oy; y-coord uses w-linspace at ox.
        int oy = 2 * h + (s >> 1);
        int ox = 2 * w + (s & 1);
        float gx = fmaf((float)oy, 2.0f / 127.0f, -1.0f) + accx;
        float gy = fmaf((float)ox, 2.0f / 127.0f, -1.0f) + accy;
        float ix = fmaf(gx, 32.0f, 31.5f);   // ((g+1)*64 - 1)/2
        float iy = fmaf(gy, 32.0f, 31.5f);

        float fx = floorf(ix), fy = floorf(iy);
        int x0 = (int)fx, y0 = (int)fy;
        float wx = ix - fx, wy = iy - fy;

        int xc0 = min(max(x0, 0), Wn - 1);
        int xc1 = min(max(x0 + 1, 0), Wn - 1);
        int yc0 = min(max(y0, 0), Hn - 1);
        int yc1 = min(max(y0 + 1, 0), Hn - 1);
        unsigned dx = (unsigned)(xc1 - xc0);          // 0 or 1
        unsigned dy = (unsigned)(yc1 - yc0);
        unsigned zx0 = ((unsigned)x0       > 63u) ? 1u : 0u;
        unsigned zx1 = ((unsigned)(x0 + 1) > 63u) ? 1u : 0u;
        unsigned zy0 = ((unsigned)y0       > 63u) ? 1u : 0u;
        unsigned zy1 = ((unsigned)(y0 + 1) > 63u) ? 1u : 0u;

        unsigned idx = (unsigned)(yc0 * PADW + xc0)
                     | (dx << 14) | (dy << 15)
                     | (zx0 << 16) | (zx1 << 17)
                     | (zy0 << 18) | (zy1 << 19);
        __half2 wxy = __floats2half2_rn(wx, wy);
        uint2 rec;
        rec.x = *reinterpret_cast<unsigned int*>(&wxy);
        rec.y = idx;
        g_samp[(size_t)b * NPX + oy * OXn + ox] = rec;
    }
}

// ---------------------------------------------------------------------------
// Stage 2 (R10-measured 74.6us — protected, unchanged): bilinear blend.
// Block = (b, cg quad, pixel-quarter).
// ---------------------------------------------------------------------------
__device__ __forceinline__ void unpack4(uint2 v, float2& p01, float2& p23)
{
    p01 = __half22float2(*reinterpret_cast<const __half2*>(&v.x));
    p23 = __half22float2(*reinterpret_cast<const __half2*>(&v.y));
}

__device__ __forceinline__ float4 sample_one(const uint2* __restrict__ plane,
                                             unsigned wbits, unsigned idx)
{
    float2 wxy = __half22float2(*reinterpret_cast<const __half2*>(&wbits));
    float wx = wxy.x, wy = wxy.y;

    int base = idx & 0x3FFF;
    int dx   = (idx >> 14) & 1;
    int dy   = (idx >> 15) & 1;
    float ax0 = (idx & (1u << 16)) ? 0.0f : (1.0f - wx);
    float ax1 = (idx & (1u << 17)) ? 0.0f : wx;
    float ay0 = (idx & (1u << 18)) ? 0.0f : (1.0f - wy);
    float ay1 = (idx & (1u << 19)) ? 0.0f : wy;

    float w00 = ay0 * ax0, w01 = ay0 * ax1;
    float w10 = ay1 * ax0, w11 = ay1 * ax1;

    const uint2* r0p = plane + base;
    const uint2* r1p = r0p + (dy ? PADW : 0);
    uint2 v00 = r0p[0], v01 = r0p[dx];
    uint2 v10 = r1p[0], v11 = r1p[dx];

    float2 a01, a23, b01, b23;
    unpack4(v00, a01, a23);
    unpack4(v01, b01, b23);
    float rx = a01.x * w00 + b01.x * w01;
    float ry = a01.y * w00 + b01.y * w01;
    float rz = a23.x * w00 + b23.x * w01;
    float rw = a23.y * w00 + b23.y * w01;
    unpack4(v10, a01, a23);
    unpack4(v11, b01, b23);
    rx = fmaf(a01.x, w10, fmaf(b01.x, w11, rx));
    ry = fmaf(a01.y, w10, fmaf(b01.y, w11, ry));
    rz = fmaf(a23.x, w10, fmaf(b23.x, w11, rz));
    rw = fmaf(a23.y, w10, fmaf(b23.y, w11, rw));
    return make_float4(rx, ry, rz, rw);
}

__global__ __launch_bounds__(256, 6) void dysample_stage2(
    float* __restrict__ out)
{
    __shared__ uint2 plane[Hn * PADW];    // 33,280 B -> 6 blocks/SM

    int bid = blockIdx.x;                 // 0..4095
    int q   = bid & 3;                    // pixel quarter
    int cg  = (bid >> 2) & 63;            // channel quad
    int b   = bid >> 8;                   // batch

    // Stage the pre-packed plane: 4096 cells, 2 per thread per iter.
    const uint2* src = g_xh + ((size_t)(b * 64 + cg)) * PLANE;
#pragma unroll
    for (int k = 0; k < 8; ++k) {
        int i = k * 512 + threadIdx.x * 2;
        uint4 v = *reinterpret_cast<const uint4*>(src + i);
        int row = i >> 6, col = i & 63;
        plane[row * PADW + col]     = make_uint2(v.x, v.y);
        plane[row * PADW + col + 1] = make_uint2(v.z, v.w);
    }
    __syncthreads();

    const uint2* samp = g_samp + (size_t)b * NPX + q * 4096;
    float* o0 = out + ((size_t)(b * Cn + cg * 4)) * NPX + q * 4096;
    float* o1 = o0 + NPX;
    float* o2 = o1 + NPX;
    float* o3 = o2 + NPX;

    int p0 = threadIdx.x * 2;
    uint4 sv = *reinterpret_cast<const uint4*>(samp + p0);

#pragma unroll
    for (int it = 0; it < 8; ++it) {
        int p = it * 512 + p0;
        uint4 cur = sv;
        if (it < 7)
            sv = *reinterpret_cast<const uint4*>(samp + p + 512);

        float4 r0 = sample_one(plane, cur.x, cur.y);
        float4 r1 = sample_one(plane, cur.z, cur.w);

        // Streaming stores: output is never re-read.
        __stcs(reinterpret_cast<float2*>(o0 + p), make_float2(r0.x, r1.x));
        __stcs(reinterpret_cast<float2*>(o1 + p), make_float2(r0.y, r1.y));
        __stcs(reinterpret_cast<float2*>(o2 + p), make_float2(r0.z, r1.z));
        __stcs(reinterpret_cast<float2*>(o3 + p), make_float2(r0.w, r1.w));
    }
}

extern "C" void kernel_launch(void* const* d_in, const int* in_sizes, int n_in,
                              void* d_out, int out_size)
{
    const float* x      = (const float*)d_in[0];
    const float* weight = (const float*)d_in[1];
    const float* bias   = (const float*)d_in[2];
    float* out          = (float*)d_out;

    static cudaStream_t s_side = nullptr;
    static cudaEvent_t  ev_fork = nullptr, ev_join = nullptr;
    if (s_side == nullptr) {
        cudaStreamCreateWithFlags(&s_side, cudaStreamNonBlocking);
        cudaEventCreateWithFlags(&ev_fork, cudaEventDisableTiming);
        cudaEventCreateWithFlags(&ev_join, cudaEventDisableTiming);
    }

    // Fork: repack (side) runs concurrently with stage1 (main).
    cudaEventRecord(ev_fork, 0);
    cudaStreamWaitEvent(s_side, ev_fork, 0);

    dysample_stage1<<<1024, 256>>>(x, weight, bias);   // main: conv+descr
    dysample_repack<<<4096, 256, 0, s_side>>>(x);      // side: fp32->fp16x4

    // Join: single event — stage2 (main) already orders after stage1.
    cudaEventRecord(ev_join, s_side);
    cudaStreamWaitEvent(0, ev_join, 0);

    dysample_stage2<<<4096, 256>>>(out);               // (b, cg, quarter)
}

// round 17
// speedup vs baseline: 1.0583x; 1.0583x over previous
#include <cuda_runtime.h>
#include <cuda_fp16.h>

// Problem constants (fixed shapes):
//   x:      (16, 256, 64, 64)  fp32
//   weight: (8, 256)           fp32
//   bias:   (8,)               fp32
//   out:    (16, 256, 128, 128) fp32
#define Bn  16
#define Cn  256
#define Hn  64
#define Wn  64
#define OYn 128
#define OXn 128
#define PLANE (Hn * Wn)        // 4096
#define PADW 65                // padded row stride (uint2 cells), y-major
#define NPX  (OYn * OXn)       // 16384

// fp16-packed input, 4 channels per uint2 cell: [b][cg][h*64+w]. 32 MB.
__device__ uint2 g_xh[Bn * 64 * PLANE];
// Per-pixel sample descriptor (8 B): {half2(wx,wy),
//   base(14b) | dx<<14 | dy<<15 | zx0<<16 | zx1<<17 | zy0<<18 | zy1<<19}
__device__ uint2 g_samp[Bn * NPX];

__device__ __forceinline__ uint2 packh4(float a, float b, float c, float d)
{
    __half2 lo = __floats2half2_rn(a, b);
    __half2 hi = __floats2half2_rn(c, d);
    uint2 r;
    r.x = *reinterpret_cast<unsigned int*>(&lo);
    r.y = *reinterpret_cast<unsigned int*>(&hi);
    return r;
}

// ---------------------------------------------------------------------------
// Fused producer: ONE launch, grid-branched.
//   blocks [0, 1024):     stage1 — 1x1 conv + pixel shuffle + descriptor emit
//   blocks [1024, 5120):  repack — x fp32 -> g_xh fp16x4 cells
// Independent outputs; x reads shared through L2. No stream/event machinery.
// ---------------------------------------------------------------------------
__global__ __launch_bounds__(256) void dysample_producer(
    const float* __restrict__ x,
    const float* __restrict__ weight,
    const float* __restrict__ bias)
{
    __shared__ float wt[Cn * 8];          // transposed: wt[c*8+o]
    __shared__ float part[4][64][9];      // padded -> conflict-free

    if (blockIdx.x >= 1024) {
        // ----------------- repack path (R10 form) -----------------
        int idx = (blockIdx.x - 1024) * 256 + threadIdx.x;  // 0 .. 1,048,575
        int b   = idx >> 16;
        int r   = idx & 65535;
        int cg  = r >> 10;                          // 0..63
        int pi  = (r & 1023) * 4;                   // pixel base

        const float* p0 = x + ((size_t)b * Cn + (size_t)cg * 4) * PLANE + pi;
        float4 a = *reinterpret_cast<const float4*>(p0);
        float4 c = *reinterpret_cast<const float4*>(p0 + PLANE);
        float4 d = *reinterpret_cast<const float4*>(p0 + 2 * PLANE);
        float4 e = *reinterpret_cast<const float4*>(p0 + 3 * PLANE);

        uint2* dst = g_xh + ((size_t)(b * 64 + cg)) * PLANE + pi;
        uint2 c0 = packh4(a.x, c.x, d.x, e.x);
        uint2 c1 = packh4(a.y, c.y, d.y, e.y);
        uint2 c2 = packh4(a.z, c.z, d.z, e.z);
        uint2 c3 = packh4(a.w, c.w, d.w, e.w);
        *reinterpret_cast<uint4*>(dst)     = make_uint4(c0.x, c0.y, c1.x, c1.y);
        *reinterpret_cast<uint4*>(dst + 2) = make_uint4(c2.x, c2.y, c3.x, c3.y);
        return;
    }

    // ----------------- stage1 path (R10 lean form) -----------------
    for (int i = threadIdx.x; i < Cn * 8; i += 256)
        wt[(i & 255) * 8 + (i >> 8)] = weight[i];
    __syncthreads();

    int w     = threadIdx.x & 63;
    int cpart = threadIdx.x >> 6;         // 0..3
    int b     = blockIdx.x >> 6;
    int h     = blockIdx.x & 63;

    const float* xb  = x + ((size_t)b * Cn + cpart * 64) * PLANE + h * Wn + w;
    const float* wr0 = &wt[(cpart * 64) * 8];

    float acc[8];
#pragma unroll
    for (int s = 0; s < 8; s++) acc[s] = 0.0f;

#pragma unroll 8
    for (int c = 0; c < 64; ++c) {
        float xv = __ldg(xb + (size_t)c * PLANE);       // coalesced along w
        float4 wa = *reinterpret_cast<const float4*>(wr0 + c * 8);
        float4 wb = *reinterpret_cast<const float4*>(wr0 + c * 8 + 4);
        acc[0] = fmaf(xv, wa.x, acc[0]);
        acc[1] = fmaf(xv, wa.y, acc[1]);
        acc[2] = fmaf(xv, wa.z, acc[2]);
        acc[3] = fmaf(xv, wa.w, acc[3]);
        acc[4] = fmaf(xv, wb.x, acc[4]);
        acc[5] = fmaf(xv, wb.y, acc[5]);
        acc[6] = fmaf(xv, wb.z, acc[6]);
        acc[7] = fmaf(xv, wb.w, acc[7]);
    }

#pragma unroll
    for (int s = 0; s < 8; s++) part[cpart][w][s] = acc[s];
    __syncthreads();

    // Each cpart handles shuffle position s = cpart for its 64 w-pixels.
    {
        int s = cpart;
        float accx = part[0][w][s]     + part[1][w][s]
                   + part[2][w][s]     + part[3][w][s]     + __ldg(&bias[s]);
        float accy = part[0][w][4 + s] + part[1][w][4 + s]
                   + part[2][w][4 + s] + part[3][w][4 + s] + __ldg(&bias[4 + s]);

        // pixel shuffle: out (oy=2h+r1, ox=2w+r2), s=r1*2+r2. Reference
        // quirk: x-coord uses h-linspace at oy; y-coord uses w-linspace at ox.
        int oy = 2 * h + (s >> 1);
        int ox = 2 * w + (s & 1);
        float gx = fmaf((float)oy, 2.0f / 127.0f, -1.0f) + accx;
        float gy = fmaf((float)ox, 2.0f / 127.0f, -1.0f) + accy;
        float ix = fmaf(gx, 32.0f, 31.5f);   // ((g+1)*64 - 1)/2
        float iy = fmaf(gy, 32.0f, 31.5f);

        float fx = floorf(ix), fy = floorf(iy);
        int x0 = (int)fx, y0 = (int)fy;
        float wx = ix - fx, wy = iy - fy;

        int xc0 = min(max(x0, 0), Wn - 1);
        int xc1 = min(max(x0 + 1, 0), Wn - 1);
        int yc0 = min(max(y0, 0), Hn - 1);
        int yc1 = min(max(y0 + 1, 0), Hn - 1);
        unsigned dx = (unsigned)(xc1 - xc0);          // 0 or 1
        unsigned dy = (unsigned)(yc1 - yc0);
        unsigned zx0 = ((unsigned)x0       > 63u) ? 1u : 0u;
        unsigned zx1 = ((unsigned)(x0 + 1) > 63u) ? 1u : 0u;
        unsigned zy0 = ((unsigned)y0       > 63u) ? 1u : 0u;
        unsigned zy1 = ((unsigned)(y0 + 1) > 63u) ? 1u : 0u;

        unsigned idx = (unsigned)(yc0 * PADW + xc0)
                     | (dx << 14) | (dy << 15)
                     | (zx0 << 16) | (zx1 << 17)
                     | (zy0 << 18) | (zy1 << 19);
        __half2 wxy = __floats2half2_rn(wx, wy);
        uint2 rec;
        rec.x = *reinterpret_cast<unsigned int*>(&wxy);
        rec.y = idx;
        g_samp[(size_t)b * NPX + oy * OXn + ox] = rec;
    }
}

// ---------------------------------------------------------------------------
// Stage 2 (R10-measured 74.6us — protected, unchanged): bilinear blend.
// Block = (b, cg quad, pixel-quarter).
// ---------------------------------------------------------------------------
__device__ __forceinline__ void unpack4(uint2 v, float2& p01, float2& p23)
{
    p01 = __half22float2(*reinterpret_cast<const __half2*>(&v.x));
    p23 = __half22float2(*reinterpret_cast<const __half2*>(&v.y));
}

__device__ __forceinline__ float4 sample_one(const uint2* __restrict__ plane,
                                             unsigned wbits, unsigned idx)
{
    float2 wxy = __half22float2(*reinterpret_cast<const __half2*>(&wbits));
    float wx = wxy.x, wy = wxy.y;

    int base = idx & 0x3FFF;
    int dx   = (idx >> 14) & 1;
    int dy   = (idx >> 15) & 1;
    float ax0 = (idx & (1u << 16)) ? 0.0f : (1.0f - wx);
    float ax1 = (idx & (1u << 17)) ? 0.0f : wx;
    float ay0 = (idx & (1u << 18)) ? 0.0f : (1.0f - wy);
    float ay1 = (idx & (1u << 19)) ? 0.0f : wy;

    float w00 = ay0 * ax0, w01 = ay0 * ax1;
    float w10 = ay1 * ax0, w11 = ay1 * ax1;

    const uint2* r0p = plane + base;
    const uint2* r1p = r0p + (dy ? PADW : 0);
    uint2 v00 = r0p[0], v01 = r0p[dx];
    uint2 v10 = r1p[0], v11 = r1p[dx];

    float2 a01, a23, b01, b23;
    unpack4(v00, a01, a23);
    unpack4(v01, b01, b23);
    float rx = a01.x * w00 + b01.x * w01;
    float ry = a01.y * w00 + b01.y * w01;
    float rz = a23.x * w00 + b23.x * w01;
    float rw = a23.y * w00 + b23.y * w01;
    unpack4(v10, a01, a23);
    unpack4(v11, b01, b23);
    rx = fmaf(a01.x, w10, fmaf(b01.x, w11, rx));
    ry = fmaf(a01.y, w10, fmaf(b01.y, w11, ry));
    rz = fmaf(a23.x, w10, fmaf(b23.x, w11, rz));
    rw = fmaf(a23.y, w10, fmaf(b23.y, w11, rw));
    return make_float4(rx, ry, rz, rw);
}

__global__ __launch_bounds__(256, 6) void dysample_stage2(
    float* __restrict__ out)
{
    __shared__ uint2 plane[Hn * PADW];    // 33,280 B -> 6 blocks/SM

    int bid = blockIdx.x;                 // 0..4095
    int q   = bid & 3;                    // pixel quarter
    int cg  = (bid >> 2) & 63;            // channel quad
    int b   = bid >> 8;                   // batch

    // Stage the pre-packed plane: 4096 cells, 2 per thread per iter.
    const uint2* src = g_xh + ((size_t)(b * 64 + cg)) * PLANE;
#pragma unroll
    for (int k = 0; k < 8; ++k) {
        int i = k * 512 + threadIdx.x * 2;
        uint4 v = *reinterpret_cast<const uint4*>(src + i);
        int row = i >> 6, col = i & 63;
        plane[row * PADW + col]     = make_uint2(v.x, v.y);
        plane[row * PADW + col + 1] = make_uint2(v.z, v.w);
    }
    __syncthreads();

    const uint2* samp = g_samp + (size_t)b * NPX + q * 4096;
    float* o0 = out + ((size_t)(b * Cn + cg * 4)) * NPX + q * 4096;
    float* o1 = o0 + NPX;
    float* o2 = o1 + NPX;
    float* o3 = o2 + NPX;

    int p0 = threadIdx.x * 2;
    uint4 sv = *reinterpret_cast<const uint4*>(samp + p0);

#pragma unroll
    for (int it = 0; it < 8; ++it) {
        int p = it * 512 + p0;
        uint4 cur = sv;
        if (it < 7)
            sv = *reinterpret_cast<const uint4*>(samp + p + 512);

        float4 r0 = sample_one(plane, cur.x, cur.y);
        float4 r1 = sample_one(plane, cur.z, cur.w);

        // Streaming stores: output is never re-read.
        __stcs(reinterpret_cast<float2*>(o0 + p), make_float2(r0.x, r1.x));
        __stcs(reinterpret_cast<float2*>(o1 + p), make_float2(r0.y, r1.y));
        __stcs(reinterpret_cast<float2*>(o2 + p), make_float2(r0.z, r1.z));
        __stcs(reinterpret_cast<float2*>(o3 + p), make_float2(r0.w, r1.w));
    }
}

extern "C" void kernel_launch(void* const* d_in, const int* in_sizes, int n_in,
                              void* d_out, int out_size)
{
    const float* x      = (const float*)d_in[0];
    const float* weight = (const float*)d_in[1];
    const float* bias   = (const float*)d_in[2];
    float* out          = (float*)d_out;

    // Single stream, two launches, zero event machinery.
    dysample_producer<<<5120, 256>>>(x, weight, bias); // stage1 + repack
    dysample_stage2<<<4096, 256>>>(out);               // (b, cg, quarter)
}